// round 1
// baseline (speedup 1.0000x reference)
#include <cuda_runtime.h>

// ---------------------------------------------------------------------------
// Problem dims
// ---------------------------------------------------------------------------
// B=8, CIN=128, H=W=32, COUT=128, K=3, DK=DV=64, NH=8, DKH=DVH=8
// out = concat(conv3x3(x, w_general)[B,64,32,32], conv3x3(attn, w_out)[B,64,32,32])

#define NB   8
#define NHH  8      // heads
#define LL   1024   // H*W
#define SQRT8 2.8284271247461903f

// ---------------------------------------------------------------------------
// Scratch (no allocation allowed -> __device__ globals)
// ---------------------------------------------------------------------------
__device__ float g_Q[NB * NHH * 8192];    // [b][h][dk][y][x]  (scaled by sqrt(8))
__device__ float g_K[NB * NHH * 8192];
__device__ float g_V[NB * NHH * 8192];
__device__ float g_RH[NB * NHH * 32 * 32 * 32];  // [bh][m1][n1][n2]
__device__ float g_RW[NB * NHH * 32 * 32 * 32];  // [bh][m1][n1][m2]
__device__ float g_attn[NB * 64 * LL];           // [b][h*8+d][y][x] (NCHW for final conv)

// ---------------------------------------------------------------------------
// Kernel 1: qkv 1x1 conv.  x[8,128,32,32] * w_qkv[192,128] -> Q,K,V
// grid (32 pos-chunks, 8 b), 192 threads (one per out channel)
// ---------------------------------------------------------------------------
__global__ void qkv_kernel(const float* __restrict__ x,
                           const float* __restrict__ w,
                           const float* __restrict__ bias)
{
    __shared__ float xs[128][33];   // [ci][pos], pad to kill conflicts
    const int b = blockIdx.y, chunk = blockIdx.x;
    const int tid = threadIdx.x;

    for (int i = tid; i < 128 * 32; i += blockDim.x) {
        int ci = i >> 5, p = i & 31;
        xs[ci][p] = x[(b * 128 + ci) * LL + chunk * 32 + p];
    }
    __syncthreads();

    const int oc = tid;  // 0..191
    float acc[32];
#pragma unroll
    for (int p = 0; p < 32; p++) acc[p] = 0.f;

    for (int ci = 0; ci < 128; ci++) {
        float wv = __ldg(&w[oc * 128 + ci]);
#pragma unroll
        for (int p = 0; p < 32; p++) acc[p] += wv * xs[ci][p];
    }

    float bv = bias[oc];
    float scale = 1.f;
    float* dst;
    int c;
    if (oc < 64)       { dst = g_Q; c = oc;       scale = SQRT8; }
    else if (oc < 128) { dst = g_K; c = oc - 64;  }
    else               { dst = g_V; c = oc - 128; }
    const int h = c >> 3, dk = c & 7;
    const int base = ((b * NHH + h) * 8 + dk) * LL + chunk * 32;
#pragma unroll
    for (int p = 0; p < 32; p++) dst[base + p] = (acc[p] + bv) * scale;
}

// ---------------------------------------------------------------------------
// Kernel 2: relative-logit precompute.
// RH[bh,m1,n1,n2] = sum_d Q5[bh,m1,n1,d]*krh[n2-n1+31,d]
// RW[bh,m1,n1,m2] = sum_d Q5[bh,m1,n1,d]*krw[m2-m1+31,d]
// with Q5[y,x,d] = g_Q[bh][d][y][x].
// grid (32 m1, 64 bh), 1024 threads (n1 = tid>>5 per warp, lane = n2 / m2)
// ---------------------------------------------------------------------------
__global__ void rel_kernel(const float* __restrict__ krh,
                           const float* __restrict__ krw)
{
    __shared__ float srh[63][9], srw[63][9];
    const int bh = blockIdx.y, m1 = blockIdx.x;
    const int tid = threadIdx.x;

    if (tid < 63 * 8) {
        int r = tid >> 3, d = tid & 7;
        srh[r][d] = krh[tid];
        srw[r][d] = krw[tid];
    }
    __syncthreads();

    const int n1 = tid >> 5, lane = tid & 31;
    const float* qp = g_Q + bh * 8192 + m1 * 32 + n1;  // [d] stride 1024
    float q[8];
#pragma unroll
    for (int d = 0; d < 8; d++) q[d] = qp[d * LL];

    const int ih = lane - n1 + 31;   // in [0,62]
    const int iw = lane - m1 + 31;   // in [0,62]
    float rh = 0.f, rw = 0.f;
#pragma unroll
    for (int d = 0; d < 8; d++) {
        rh += q[d] * srh[ih][d];
        rw += q[d] * srw[iw][d];
    }
    const int o = ((bh * 32 + m1) * 32 + n1) * 32 + lane;
    g_RH[o] = rh;
    g_RW[o] = rw;
}

// ---------------------------------------------------------------------------
// Kernel 3: attention. One (bh, n-chunk of 128) per block, 128 threads,
// thread owns one query row n. Flash-style online softmax, chunked by m1.
// smem: K(32KB) V(32KB) RH slice(16KB) RW slice(16KB) = 96KB dynamic.
// ---------------------------------------------------------------------------
__global__ void attn_kernel()
{
    extern __shared__ float sm[];
    float* sK  = sm;             // 8192
    float* sV  = sm + 8192;      // 8192
    float* sRH = sm + 16384;     // 4096  [m1][n1l][n2]
    float* sRW = sm + 20480;     // 4096  [m1][n1l][m2]

    const int bh = blockIdx.y;
    const int chunk = blockIdx.x;   // 0..7
    const int tid = threadIdx.x;    // 128

    const float4* Kg4 = (const float4*)(g_K + bh * 8192);
    const float4* Vg4 = (const float4*)(g_V + bh * 8192);
    float4* sK4 = (float4*)sK;
    float4* sV4 = (float4*)sV;
    for (int i = tid; i < 2048; i += 128) {
        sK4[i] = Kg4[i];
        sV4[i] = Vg4[i];
    }
    const float* RHg = g_RH + bh * 32768;
    const float* RWg = g_RW + bh * 32768;
    for (int i = tid; i < 4096; i += 128) {
        int m1 = i >> 7, r = i & 127;
        sRH[i] = RHg[m1 * 1024 + chunk * 128 + r];
        sRW[i] = RWg[m1 * 1024 + chunk * 128 + r];
    }
    __syncthreads();

    const int n = chunk * 128 + tid;
    const int n1l = tid >> 5, n2 = tid & 31;

    const float4* q4 = (const float4*)(g_Q + bh * 8192 + n * 8);
    const float4 qa = q4[0], qb = q4[1];

    float acc[8];
#pragma unroll
    for (int d = 0; d < 8; d++) acc[d] = 0.f;
    float M = -1e30f, S = 0.f;

    for (int m1 = 0; m1 < 32; m1++) {
        const float rh = sRH[(m1 << 7) + (n1l << 5) + n2];
        const float* rw = &sRW[(m1 << 7) + (n1l << 5)];
        const float4* kk = (const float4*)(sK + m1 * 256);

        float l[32];
        float cmax = -1e30f;
#pragma unroll
        for (int m2 = 0; m2 < 32; m2++) {
            float4 ka = kk[2 * m2], kb = kk[2 * m2 + 1];
            float dot = qa.x * ka.x + qa.y * ka.y + qa.z * ka.z + qa.w * ka.w
                      + qb.x * kb.x + qb.y * kb.y + qb.z * kb.z + qb.w * kb.w;
            float v = dot + rh + rw[m2];
            l[m2] = v;
            cmax = fmaxf(cmax, v);
        }
        const float Mn = fmaxf(M, cmax);
        const float corr = __expf(M - Mn);
        S *= corr;
#pragma unroll
        for (int d = 0; d < 8; d++) acc[d] *= corr;

        const float4* vv = (const float4*)(sV + m1 * 256);
#pragma unroll
        for (int m2 = 0; m2 < 32; m2++) {
            float p = __expf(l[m2] - Mn);
            S += p;
            float4 va = vv[2 * m2], vb = vv[2 * m2 + 1];
            acc[0] += p * va.x; acc[1] += p * va.y;
            acc[2] += p * va.z; acc[3] += p * va.w;
            acc[4] += p * vb.x; acc[5] += p * vb.y;
            acc[6] += p * vb.z; acc[7] += p * vb.w;
        }
        M = Mn;
    }

    const float inv = 1.f / S;
#pragma unroll
    for (int d = 0; d < 8; d++)
        g_attn[(bh * 8 + d) * LL + n] = acc[d] * inv;
}

// ---------------------------------------------------------------------------
// Kernel 4/5: 3x3 conv, stride 1, pad 1.  64 out channels.
// grid (16 row-pairs, 8 b), 256 threads. Thread: 8 oc x 2 rows x 1 col.
// smem per ci-chunk(16): weights 36.8KB + input halo tile 9.2KB (static, <48KB)
// ---------------------------------------------------------------------------
template<int CINT, bool FROM_ATTN>
__global__ void conv3x3_kernel(const float* __restrict__ xin,
                               const float* __restrict__ wt,
                               const float* __restrict__ bias,
                               float* __restrict__ out, int oc_off)
{
    constexpr int CCH = 16;
    __shared__ float ws[64 * CCH * 9];   // [oc][ci][k]
    __shared__ float xs[CCH][4][36];     // [ci][row(-1..+2)][col(-1..32)+pad]

    const float* __restrict__ src = FROM_ATTN ? (const float*)g_attn : xin;

    const int b = blockIdx.y, yp = blockIdx.x;
    const int y0 = yp * 2;
    const int tid = threadIdx.x;
    const int x = tid & 31, og = tid >> 5;   // og in [0,8)

    float acc[8][2];
#pragma unroll
    for (int o = 0; o < 8; o++) { acc[o][0] = 0.f; acc[o][1] = 0.f; }

    for (int c0 = 0; c0 < CINT; c0 += CCH) {
        __syncthreads();
        // weights: 64*16*9 = 9216 floats
        for (int i = tid; i < 64 * CCH * 9; i += 256) {
            int oc = i / (CCH * 9);
            int r  = i - oc * (CCH * 9);        // ci*9 + k
            ws[i] = wt[(oc * CINT + c0) * 9 + r];
        }
        // input tile with halo: 16*4*34
        for (int i = tid; i < CCH * 4 * 34; i += 256) {
            int ci = i / 136;
            int r2 = i - ci * 136;
            int rr = r2 / 34, col = r2 - rr * 34;
            int yy = y0 - 1 + rr, xx = col - 1;
            float v = 0.f;
            if (yy >= 0 && yy < 32 && xx >= 0 && xx < 32)
                v = src[(b * CINT + c0 + ci) * LL + yy * 32 + xx];
            xs[ci][rr][col] = v;
        }
        __syncthreads();

        for (int ci = 0; ci < CCH; ci++) {
#pragma unroll
            for (int ky = 0; ky < 3; ky++) {
                float xa0 = xs[ci][ky][x],     xa1 = xs[ci][ky][x + 1],     xa2 = xs[ci][ky][x + 2];
                float xb0 = xs[ci][ky + 1][x], xb1 = xs[ci][ky + 1][x + 1], xb2 = xs[ci][ky + 1][x + 2];
#pragma unroll
                for (int o = 0; o < 8; o++) {
                    const float* wp = &ws[((og * 8 + o) * CCH + ci) * 9 + ky * 3];
                    float w0 = wp[0], w1 = wp[1], w2 = wp[2];
                    acc[o][0] += w0 * xa0 + w1 * xa1 + w2 * xa2;
                    acc[o][1] += w0 * xb0 + w1 * xb1 + w2 * xb2;
                }
            }
        }
    }

#pragma unroll
    for (int o = 0; o < 8; o++) {
        float bv = bias[og * 8 + o];
#pragma unroll
        for (int r = 0; r < 2; r++) {
            out[(b * 128 + oc_off + og * 8 + o) * LL + (y0 + r) * 32 + x] = acc[o][r] + bv;
        }
    }
}

// ---------------------------------------------------------------------------
// Launch
// ---------------------------------------------------------------------------
extern "C" void kernel_launch(void* const* d_in, const int* in_sizes, int n_in,
                              void* d_out, int out_size)
{
    const float* x         = (const float*)d_in[0];
    const float* w_general = (const float*)d_in[1];
    const float* b_general = (const float*)d_in[2];
    const float* w_qkv     = (const float*)d_in[3];
    const float* b_qkv     = (const float*)d_in[4];
    const float* w_out     = (const float*)d_in[5];
    const float* b_out     = (const float*)d_in[6];
    const float* krh       = (const float*)d_in[7];
    const float* krw       = (const float*)d_in[8];
    float* out = (float*)d_out;

    cudaFuncSetAttribute(attn_kernel,
                         cudaFuncAttributeMaxDynamicSharedMemorySize, 98304);

    // independent branch: conv_general -> out channels [0,64)
    conv3x3_kernel<128, false><<<dim3(16, NB), 256>>>(x, w_general, b_general, out, 0);

    // attention branch
    qkv_kernel<<<dim3(32, NB), 192>>>(x, w_qkv, b_qkv);
    rel_kernel<<<dim3(32, NB * NHH), 1024>>>(krh, krw);
    attn_kernel<<<dim3(8, NB * NHH), 128, 98304>>>();
    conv3x3_kernel<64, true><<<dim3(16, NB), 256>>>(nullptr, w_out, b_out, out, 64);
}

// round 2
// speedup vs baseline: 1.1417x; 1.1417x over previous
#include <cuda_runtime.h>

#define NB   8
#define NHH  8
#define LL   1024
#define SQRT8 2.8284271247461903f

// ---------------------------------------------------------------------------
// f32x2 helpers (Blackwell packed fp32)
// ---------------------------------------------------------------------------
__device__ __forceinline__ unsigned long long pk2(float a, float b) {
    unsigned long long r;
    asm("mov.b64 %0, {%1,%2};" : "=l"(r) : "f"(a), "f"(b));
    return r;
}
__device__ __forceinline__ void upk2(unsigned long long v, float& a, float& b) {
    asm("mov.b64 {%0,%1}, %2;" : "=f"(a), "=f"(b) : "l"(v));
}
__device__ __forceinline__ unsigned long long fma2(unsigned long long a,
                                                   unsigned long long b,
                                                   unsigned long long c) {
    unsigned long long r;
    asm("fma.rn.f32x2 %0, %1, %2, %3;" : "=l"(r) : "l"(a), "l"(b), "l"(c));
    return r;
}

// ---------------------------------------------------------------------------
// Scratch
// ---------------------------------------------------------------------------
__device__ float g_Q[NB * NHH * 8192];    // [bh][dk][y][x], scaled by sqrt(8)
__device__ float g_K[NB * NHH * 8192];
__device__ float g_V[NB * NHH * 8192];
__device__ float g_RH[NB * NHH * 32768];  // [bh][m1][n1][n2]
__device__ float g_RW[NB * NHH * 32768];  // [bh][m1][n1][m2]
__device__ float g_attn[NB * 64 * LL];    // NCHW for final conv

// ---------------------------------------------------------------------------
// Kernel 1: qkv 1x1 conv (f32x2 over position pairs)
// grid (32 pos-chunks, 8 b), 192 threads (one per out channel)
// ---------------------------------------------------------------------------
__global__ void __launch_bounds__(192) qkv_kernel(const float* __restrict__ x,
                                                  const float* __restrict__ w,
                                                  const float* __restrict__ bias)
{
    __shared__ float xs[128][36];   // 36 -> 144B row stride (16B multiple)
    const int b = blockIdx.y, chunk = blockIdx.x;
    const int tid = threadIdx.x;

    for (int i = tid; i < 128 * 32; i += 192) {
        int ci = i >> 5, p = i & 31;
        xs[ci][p] = x[(b * 128 + ci) * LL + chunk * 32 + p];
    }
    __syncthreads();

    const int oc = tid;
    unsigned long long acc[16];
#pragma unroll
    for (int j = 0; j < 16; j++) acc[j] = 0ull;

    for (int ci = 0; ci < 128; ci++) {
        float wv = __ldg(&w[oc * 128 + ci]);
        unsigned long long w2 = pk2(wv, wv);
        const ulonglong2* row = (const ulonglong2*)&xs[ci][0];
#pragma unroll
        for (int j = 0; j < 8; j++) {
            ulonglong2 xv = row[j];
            acc[2 * j]     = fma2(w2, xv.x, acc[2 * j]);
            acc[2 * j + 1] = fma2(w2, xv.y, acc[2 * j + 1]);
        }
    }

    float bv = bias[oc];
    float scale = 1.f;
    float* dst;
    int c;
    if (oc < 64)       { dst = g_Q; c = oc;       scale = SQRT8; }
    else if (oc < 128) { dst = g_K; c = oc - 64;  }
    else               { dst = g_V; c = oc - 128; }
    const int h = c >> 3, dk = c & 7;
    const int base = ((b * NHH + h) * 8 + dk) * LL + chunk * 32;
#pragma unroll
    for (int j = 0; j < 16; j++) {
        float a, bb;
        upk2(acc[j], a, bb);
        dst[base + 2 * j]     = (a  + bv) * scale;
        dst[base + 2 * j + 1] = (bb + bv) * scale;
    }
}

// ---------------------------------------------------------------------------
// Kernel 2: relative-logit precompute (unchanged; small)
// ---------------------------------------------------------------------------
__global__ void rel_kernel(const float* __restrict__ krh,
                           const float* __restrict__ krw)
{
    __shared__ float srh[63][9], srw[63][9];
    const int bh = blockIdx.y, m1 = blockIdx.x;
    const int tid = threadIdx.x;

    if (tid < 63 * 8) {
        int r = tid >> 3, d = tid & 7;
        srh[r][d] = krh[tid];
        srw[r][d] = krw[tid];
    }
    __syncthreads();

    const int n1 = tid >> 5, lane = tid & 31;
    const float* qp = g_Q + bh * 8192 + m1 * 32 + n1;
    float q[8];
#pragma unroll
    for (int d = 0; d < 8; d++) q[d] = qp[d * LL];

    const int ih = lane - n1 + 31;
    const int iw = lane - m1 + 31;
    float rh = 0.f, rw = 0.f;
#pragma unroll
    for (int d = 0; d < 8; d++) {
        rh += q[d] * srh[ih][d];
        rw += q[d] * srw[iw][d];
    }
    const int o = ((bh * 32 + m1) * 32 + n1) * 32 + lane;
    g_RH[o] = rh;
    g_RW[o] = rw;
}

// ---------------------------------------------------------------------------
// Kernel 3: attention. 128 threads, 2 queries/thread (256 q per block).
// grid (4, 64) = 256 CTAs, 96KB smem -> 2 CTAs/SM, single wave.
// No online max: logits bounded (~|35|), exp(v-18) safe in fp32.
// smem: K 32KB + V 32KB + RW slice 32KB.
// ---------------------------------------------------------------------------
__global__ void __launch_bounds__(128) attn_kernel()
{
    extern __shared__ float sm[];
    float* sK  = sm;             // 8192 floats
    float* sV  = sm + 8192;      // 8192
    float* sRW = sm + 16384;     // 8192  [m1][ln1(8)][m2]

    const int bh = blockIdx.y;
    const int chunk = blockIdx.x;   // 0..3, 256 queries each
    const int tid = threadIdx.x;

    const float4* Kg4 = (const float4*)(g_K + bh * 8192);
    const float4* Vg4 = (const float4*)(g_V + bh * 8192);
    float4* sK4 = (float4*)sK;
    float4* sV4 = (float4*)sV;
    for (int i = tid; i < 2048; i += 128) {
        sK4[i] = Kg4[i];
        sV4[i] = Vg4[i];
    }
    const float* RWg = g_RW + bh * 32768 + chunk * 256;
    for (int i = tid; i < 8192; i += 128)
        sRW[i] = RWg[(i >> 8) * 1024 + (i & 255)];
    __syncthreads();

    const int n0 = chunk * 256 + 2 * tid;   // even
    const int ln1 = tid >> 4;               // local n1 (0..7)
    const float* RHg = g_RH + bh * 32768;

    const ulonglong2* qg = (const ulonglong2*)(g_Q + bh * 8192 + n0 * 8);
    ulonglong2 qa = qg[0], qb = qg[1];      // query 0
    ulonglong2 qc = qg[2], qd = qg[3];      // query 1
    unsigned long long q0[4] = { qa.x, qa.y, qb.x, qb.y };
    unsigned long long q1[4] = { qc.x, qc.y, qd.x, qd.y };

    unsigned long long acc0[4] = {0,0,0,0}, acc1[4] = {0,0,0,0};
    float S0 = 0.f, S1 = 0.f;

    for (int m1 = 0; m1 < 32; m1++) {
        float2 rh = *(const float2*)(RHg + m1 * 1024 + n0);
        const float rh0 = rh.x - 18.f;
        const float rh1 = rh.y - 18.f;
        const float* rwp = sRW + m1 * 256 + ln1 * 32;
        const float* kb = sK + m1 * 256;
        const float* vb = sV + m1 * 256;

#pragma unroll 8
        for (int m2 = 0; m2 < 32; m2++) {
            ulonglong2 ka = *(const ulonglong2*)(kb + m2 * 8);
            ulonglong2 kc = *(const ulonglong2*)(kb + m2 * 8 + 4);
            float rw = rwp[m2];

            unsigned long long d0 = pk2(rh0, rw);
            d0 = fma2(q0[0], ka.x, d0);
            d0 = fma2(q0[1], ka.y, d0);
            d0 = fma2(q0[2], kc.x, d0);
            d0 = fma2(q0[3], kc.y, d0);
            unsigned long long d1 = pk2(rh1, rw);
            d1 = fma2(q1[0], ka.x, d1);
            d1 = fma2(q1[1], ka.y, d1);
            d1 = fma2(q1[2], kc.x, d1);
            d1 = fma2(q1[3], kc.y, d1);

            float a, b;
            upk2(d0, a, b);
            float p0 = __expf(a + b);
            upk2(d1, a, b);
            float p1 = __expf(a + b);
            S0 += p0;
            S1 += p1;
            unsigned long long P0 = pk2(p0, p0);
            unsigned long long P1 = pk2(p1, p1);

            ulonglong2 va = *(const ulonglong2*)(vb + m2 * 8);
            ulonglong2 vc = *(const ulonglong2*)(vb + m2 * 8 + 4);
            acc0[0] = fma2(P0, va.x, acc0[0]);
            acc0[1] = fma2(P0, va.y, acc0[1]);
            acc0[2] = fma2(P0, vc.x, acc0[2]);
            acc0[3] = fma2(P0, vc.y, acc0[3]);
            acc1[0] = fma2(P1, va.x, acc1[0]);
            acc1[1] = fma2(P1, va.y, acc1[1]);
            acc1[2] = fma2(P1, vc.x, acc1[2]);
            acc1[3] = fma2(P1, vc.y, acc1[3]);
        }
    }

    const float i0 = 1.f / S0, i1 = 1.f / S1;
#pragma unroll
    for (int j = 0; j < 4; j++) {
        float a, b;
        upk2(acc0[j], a, b);
        g_attn[(bh * 8 + 2 * j) * LL + n0]     = a * i0;
        g_attn[(bh * 8 + 2 * j + 1) * LL + n0] = b * i0;
        upk2(acc1[j], a, b);
        g_attn[(bh * 8 + 2 * j) * LL + n0 + 1]     = a * i1;
        g_attn[(bh * 8 + 2 * j + 1) * LL + n0 + 1] = b * i1;
    }
}

// ---------------------------------------------------------------------------
// Kernel 4/5: 3x3 conv with f32x2 over output-channel pairs.
// grid (16 row-pairs, 8 b), 256 threads: 32 cols x 8 oc-groups.
// Thread: 4 oc-pairs x 2 rows. Weights staged [ci][k][oc] so pairs load
// as one broadcast LDS.128 (2 pairs).
// ---------------------------------------------------------------------------
template<int CINT, bool FROM_ATTN>
__global__ void __launch_bounds__(256) conv3x3_kernel(const float* __restrict__ xin,
                                                      const float* __restrict__ wt,
                                                      const float* __restrict__ bias,
                                                      float* __restrict__ out, int oc_off)
{
    constexpr int CCH = 16;
    __shared__ float ws[CCH * 9 * 64];   // [ci][k][oc]
    __shared__ float xs[CCH][4][36];     // [ci][row -1..+2][col -1..32 +pad]

    const float* __restrict__ src = FROM_ATTN ? (const float*)g_attn : xin;

    const int b = blockIdx.y, y0 = blockIdx.x * 2;
    const int tid = threadIdx.x;
    const int x = tid & 31, og = tid >> 5;

    unsigned long long acc[4][2];
#pragma unroll
    for (int p = 0; p < 4; p++) { acc[p][0] = 0ull; acc[p][1] = 0ull; }

    for (int c0 = 0; c0 < CINT; c0 += CCH) {
        __syncthreads();
        // stage weights: ws[(ci*9+k)*64 + oc] = wt[(oc*CINT + c0+ci)*9 + k]
        for (int i = tid; i < CCH * 9 * 64; i += 256) {
            int oc = i & 63;
            int r  = i >> 6;          // ci*9 + k
            int k  = r % 9, ci = r / 9;
            ws[i] = wt[(oc * CINT + c0 + ci) * 9 + k];
        }
        // stage input tile with halo
        for (int i = tid; i < CCH * 4 * 34; i += 256) {
            int ci = i / 136;
            int r2 = i - ci * 136;
            int rr = r2 / 34, col = r2 - rr * 34;
            int yy = y0 - 1 + rr, xx = col - 1;
            float v = 0.f;
            if (yy >= 0 && yy < 32 && xx >= 0 && xx < 32)
                v = src[(b * CINT + c0 + ci) * LL + yy * 32 + xx];
            xs[ci][rr][col] = v;
        }
        __syncthreads();

        for (int ci = 0; ci < CCH; ci++) {
            // 12 input taps (4 rows x 3 cols), splatted to f32x2
            unsigned long long x2[4][3];
#pragma unroll
            for (int rr = 0; rr < 4; rr++)
#pragma unroll
                for (int c = 0; c < 3; c++) {
                    float v = xs[ci][rr][x + c];
                    x2[rr][c] = pk2(v, v);
                }
            const float* wp = &ws[ci * 9 * 64 + og * 8];
#pragma unroll
            for (int k = 0; k < 9; k++) {
                const int ky = k / 3, c = k - ky * 3;
                ulonglong2 wA = *(const ulonglong2*)(wp + k * 64);      // pairs 0,1
                ulonglong2 wB = *(const ulonglong2*)(wp + k * 64 + 4);  // pairs 2,3
                acc[0][0] = fma2(wA.x, x2[ky][c],     acc[0][0]);
                acc[0][1] = fma2(wA.x, x2[ky + 1][c], acc[0][1]);
                acc[1][0] = fma2(wA.y, x2[ky][c],     acc[1][0]);
                acc[1][1] = fma2(wA.y, x2[ky + 1][c], acc[1][1]);
                acc[2][0] = fma2(wB.x, x2[ky][c],     acc[2][0]);
                acc[2][1] = fma2(wB.x, x2[ky + 1][c], acc[2][1]);
                acc[3][0] = fma2(wB.y, x2[ky][c],     acc[3][0]);
                acc[3][1] = fma2(wB.y, x2[ky + 1][c], acc[3][1]);
            }
        }
    }

#pragma unroll
    for (int p = 0; p < 4; p++) {
        const int oc0 = og * 8 + 2 * p;
        float b0 = bias[oc0], b1 = bias[oc0 + 1];
#pragma unroll
        for (int r = 0; r < 2; r++) {
            float a, bb;
            upk2(acc[p][r], a, bb);
            out[(b * 128 + oc_off + oc0) * LL + (y0 + r) * 32 + x]     = a + b0;
            out[(b * 128 + oc_off + oc0 + 1) * LL + (y0 + r) * 32 + x] = bb + b1;
        }
    }
}

// ---------------------------------------------------------------------------
// Launch
// ---------------------------------------------------------------------------
extern "C" void kernel_launch(void* const* d_in, const int* in_sizes, int n_in,
                              void* d_out, int out_size)
{
    const float* x         = (const float*)d_in[0];
    const float* w_general = (const float*)d_in[1];
    const float* b_general = (const float*)d_in[2];
    const float* w_qkv     = (const float*)d_in[3];
    const float* b_qkv     = (const float*)d_in[4];
    const float* w_out     = (const float*)d_in[5];
    const float* b_out     = (const float*)d_in[6];
    const float* krh       = (const float*)d_in[7];
    const float* krw       = (const float*)d_in[8];
    float* out = (float*)d_out;

    cudaFuncSetAttribute(attn_kernel,
                         cudaFuncAttributeMaxDynamicSharedMemorySize, 98304);

    conv3x3_kernel<128, false><<<dim3(16, NB), 256>>>(x, w_general, b_general, out, 0);

    qkv_kernel<<<dim3(32, NB), 192>>>(x, w_qkv, b_qkv);
    rel_kernel<<<dim3(32, NB * NHH), 1024>>>(krh, krw);
    attn_kernel<<<dim3(4, NB * NHH), 128, 98304>>>();
    conv3x3_kernel<64, true><<<dim3(16, NB), 256>>>(nullptr, w_out, b_out, out, 64);
}

// round 3
// speedup vs baseline: 1.2443x; 1.0899x over previous
#include <cuda_runtime.h>

#define NB   8
#define NHH  8
#define LL   1024
#define SQRT8 2.8284271247461903f

// ---------------------------------------------------------------------------
// f32x2 helpers
// ---------------------------------------------------------------------------
__device__ __forceinline__ unsigned long long pk2(float a, float b) {
    unsigned long long r;
    asm("mov.b64 %0, {%1,%2};" : "=l"(r) : "f"(a), "f"(b));
    return r;
}
__device__ __forceinline__ void upk2(unsigned long long v, float& a, float& b) {
    asm("mov.b64 {%0,%1}, %2;" : "=f"(a), "=f"(b) : "l"(v));
}
__device__ __forceinline__ unsigned long long fma2(unsigned long long a,
                                                   unsigned long long b,
                                                   unsigned long long c) {
    unsigned long long r;
    asm("fma.rn.f32x2 %0, %1, %2, %3;" : "=l"(r) : "l"(a), "l"(b), "l"(c));
    return r;
}

// ---------------------------------------------------------------------------
// Scratch
// ---------------------------------------------------------------------------
__device__ float g_Q[NB * NHH * 8192];
__device__ float g_K[NB * NHH * 8192];
__device__ float g_V[NB * NHH * 8192];
__device__ float g_RH[NB * NHH * 32768];   // [bh][m1][n1][n2]
__device__ float g_RW[NB * NHH * 32768];   // [bh][m1][n1][m2]
__device__ float g_attn[NB * 64 * LL];
__device__ float g_pacc[2 * 64 * 8 * LL];  // [split][bh][d][n]
__device__ float g_pS[2 * 64 * LL];        // [split][bh][n]

// ---------------------------------------------------------------------------
// Kernel 1: qkv 1x1 conv.  grid(32,8), 192 threads.
// ---------------------------------------------------------------------------
__global__ void __launch_bounds__(192) qkv_kernel(const float* __restrict__ x,
                                                  const float* __restrict__ w,
                                                  const float* __restrict__ bias)
{
    __shared__ float xs[128][36];
    const int b = blockIdx.y, chunk = blockIdx.x;
    const int tid = threadIdx.x;

    for (int i = tid; i < 128 * 32; i += 192) {
        int ci = i >> 5, p = i & 31;
        xs[ci][p] = x[(b * 128 + ci) * LL + chunk * 32 + p];
    }
    __syncthreads();

    const int oc = tid;
    unsigned long long acc[16];
#pragma unroll
    for (int j = 0; j < 16; j++) acc[j] = 0ull;

    const float4* wrow = (const float4*)(w + oc * 128);
#pragma unroll 8
    for (int c4 = 0; c4 < 32; c4++) {
        float4 w4 = __ldg(&wrow[c4]);
#pragma unroll
        for (int s = 0; s < 4; s++) {
            float wv = (s == 0) ? w4.x : (s == 1) ? w4.y : (s == 2) ? w4.z : w4.w;
            unsigned long long w2 = pk2(wv, wv);
            const ulonglong2* row = (const ulonglong2*)&xs[c4 * 4 + s][0];
#pragma unroll
            for (int j = 0; j < 8; j++) {
                ulonglong2 xv = row[j];
                acc[2 * j]     = fma2(w2, xv.x, acc[2 * j]);
                acc[2 * j + 1] = fma2(w2, xv.y, acc[2 * j + 1]);
            }
        }
    }

    float bv = bias[oc];
    float scale = 1.f;
    float* dst;
    int c;
    if (oc < 64)       { dst = g_Q; c = oc;       scale = SQRT8; }
    else if (oc < 128) { dst = g_K; c = oc - 64;  }
    else               { dst = g_V; c = oc - 128; }
    const int h = c >> 3, dk = c & 7;
    const int base = ((b * NHH + h) * 8 + dk) * LL + chunk * 32;
#pragma unroll
    for (int j = 0; j < 16; j++) {
        float a, bb;
        upk2(acc[j], a, bb);
        dst[base + 2 * j]     = (a  + bv) * scale;
        dst[base + 2 * j + 1] = (bb + bv) * scale;
    }
}

// ---------------------------------------------------------------------------
// Kernel 2: relative-logit precompute
// ---------------------------------------------------------------------------
__global__ void rel_kernel(const float* __restrict__ krh,
                           const float* __restrict__ krw)
{
    __shared__ float srh[63][9], srw[63][9];
    const int bh = blockIdx.y, m1 = blockIdx.x;
    const int tid = threadIdx.x;

    if (tid < 63 * 8) {
        int r = tid >> 3, d = tid & 7;
        srh[r][d] = krh[tid];
        srw[r][d] = krw[tid];
    }
    __syncthreads();

    const int n1 = tid >> 5, lane = tid & 31;
    const float* qp = g_Q + bh * 8192 + m1 * 32 + n1;
    float q[8];
#pragma unroll
    for (int d = 0; d < 8; d++) q[d] = qp[d * LL];

    const int ih = lane - n1 + 31;
    const int iw = lane - m1 + 31;
    float rh = 0.f, rw = 0.f;
#pragma unroll
    for (int d = 0; d < 8; d++) {
        rh += q[d] * srh[ih][d];
        rw += q[d] * srw[iw][d];
    }
    const int o = ((bh * 32 + m1) * 32 + n1) * 32 + lane;
    g_RH[o] = rh;
    g_RW[o] = rw;
}

// ---------------------------------------------------------------------------
// Kernel 3: attention, split-K.
// grid(8, 64): blockIdx.x = split*4 + chunk. 128 threads, 2 queries/thread.
// CTA: 256 queries x 512 keys. smem 50KB -> 4 CTAs/SM, 4 warps/SMSP.
// ---------------------------------------------------------------------------
__global__ void __launch_bounds__(128) attn_kernel()
{
    extern __shared__ float sm[];
    float* sK  = sm;            // 4096
    float* sV  = sm + 4096;     // 4096
    float* sRW = sm + 8192;     // 16*8*36 = 4608 (padded rows)

    const int bh = blockIdx.y;
    const int chunk = blockIdx.x & 3;
    const int split = blockIdx.x >> 2;
    const int tid = threadIdx.x;

    const float4* Kg4 = (const float4*)(g_K + bh * 8192 + split * 4096);
    const float4* Vg4 = (const float4*)(g_V + bh * 8192 + split * 4096);
    float4* sK4 = (float4*)sK;
    float4* sV4 = (float4*)sV;
    for (int i = tid; i < 1024; i += 128) {
        sK4[i] = Kg4[i];
        sV4[i] = Vg4[i];
    }
    const float* RWg = g_RW + bh * 32768 + split * 16384 + chunk * 256;
    for (int i = tid; i < 16 * 8 * 32; i += 128) {
        int m1l = i >> 8, r = i & 255;
        int n1l = r >> 5, m2 = r & 31;
        sRW[(m1l * 8 + n1l) * 36 + m2] = RWg[m1l * 1024 + n1l * 32 + m2];
    }
    __syncthreads();

    const int n1l = tid >> 4, j = tid & 15;
    const int n0 = chunk * 256 + n1l * 32 + j;   // query 0; query 1 = n0+16
    const float* RHg = g_RH + bh * 32768 + split * 16384;

    const ulonglong2* qg = (const ulonglong2*)(g_Q + bh * 8192 + n0 * 8);
    ulonglong2 qa = qg[0], qb = qg[1];
    const ulonglong2* qh = (const ulonglong2*)(g_Q + bh * 8192 + (n0 + 16) * 8);
    ulonglong2 qc = qh[0], qd = qh[1];
    unsigned long long q0[4] = { qa.x, qa.y, qb.x, qb.y };
    unsigned long long q1[4] = { qc.x, qc.y, qd.x, qd.y };

    unsigned long long acc0[4] = {0,0,0,0}, acc1[4] = {0,0,0,0};
    float S0 = 0.f, S1 = 0.f;

    float rh0 = RHg[n0] - 18.f;
    float rh1 = RHg[n0 + 16] - 18.f;

    for (int m1l = 0; m1l < 16; m1l++) {
        // prefetch next rh
        const int nx = (m1l < 15) ? (m1l + 1) : 15;
        float nrh0 = RHg[nx * 1024 + n0];
        float nrh1 = RHg[nx * 1024 + n0 + 16];

        const float* rwp = sRW + (m1l * 8 + n1l) * 36;
        const float* kb = sK + m1l * 256;
        const float* vb = sV + m1l * 256;

#pragma unroll 8
        for (int m2 = 0; m2 < 32; m2++) {
            ulonglong2 ka = *(const ulonglong2*)(kb + m2 * 8);
            ulonglong2 kc = *(const ulonglong2*)(kb + m2 * 8 + 4);
            float rw = rwp[m2];

            unsigned long long d0 = pk2(rh0, rw);
            d0 = fma2(q0[0], ka.x, d0);
            d0 = fma2(q0[1], ka.y, d0);
            d0 = fma2(q0[2], kc.x, d0);
            d0 = fma2(q0[3], kc.y, d0);
            unsigned long long d1 = pk2(rh1, rw);
            d1 = fma2(q1[0], ka.x, d1);
            d1 = fma2(q1[1], ka.y, d1);
            d1 = fma2(q1[2], kc.x, d1);
            d1 = fma2(q1[3], kc.y, d1);

            float a, b;
            upk2(d0, a, b);
            float p0 = __expf(a + b);
            upk2(d1, a, b);
            float p1 = __expf(a + b);
            S0 += p0;
            S1 += p1;
            unsigned long long P0 = pk2(p0, p0);
            unsigned long long P1 = pk2(p1, p1);

            ulonglong2 va = *(const ulonglong2*)(vb + m2 * 8);
            ulonglong2 vc = *(const ulonglong2*)(vb + m2 * 8 + 4);
            acc0[0] = fma2(P0, va.x, acc0[0]);
            acc0[1] = fma2(P0, va.y, acc0[1]);
            acc0[2] = fma2(P0, vc.x, acc0[2]);
            acc0[3] = fma2(P0, vc.y, acc0[3]);
            acc1[0] = fma2(P1, va.x, acc1[0]);
            acc1[1] = fma2(P1, va.y, acc1[1]);
            acc1[2] = fma2(P1, vc.x, acc1[2]);
            acc1[3] = fma2(P1, vc.y, acc1[3]);
        }
        rh0 = nrh0 - 18.f;
        rh1 = nrh1 - 18.f;
    }

    const int pb = (split * 64 + bh);
#pragma unroll
    for (int jj = 0; jj < 4; jj++) {
        float a, b;
        upk2(acc0[jj], a, b);
        g_pacc[(pb * 8 + 2 * jj) * LL + n0]     = a;
        g_pacc[(pb * 8 + 2 * jj + 1) * LL + n0] = b;
        upk2(acc1[jj], a, b);
        g_pacc[(pb * 8 + 2 * jj) * LL + n0 + 16]     = a;
        g_pacc[(pb * 8 + 2 * jj + 1) * LL + n0 + 16] = b;
    }
    g_pS[pb * LL + n0]      = S0;
    g_pS[pb * LL + n0 + 16] = S1;
}

// ---------------------------------------------------------------------------
// Kernel 3b: split-K combine -> g_attn (NCHW)
// ---------------------------------------------------------------------------
__global__ void __launch_bounds__(256) combine_kernel()
{
    const int idx = blockIdx.x * 256 + threadIdx.x;   // 65536 total
    const int bh = idx >> 10, n = idx & 1023;
    const float S = g_pS[bh * LL + n] + g_pS[(64 + bh) * LL + n];
    const float inv = 1.f / S;
#pragma unroll
    for (int d = 0; d < 8; d++) {
        float a = g_pacc[(bh * 8 + d) * LL + n] + g_pacc[((64 + bh) * 8 + d) * LL + n];
        g_attn[(bh * 8 + d) * LL + n] = a * inv;
    }
}

// ---------------------------------------------------------------------------
// Kernel 4/5: 3x3 conv, oc-split. grid(16 rowpairs, 8 b, 2 oc-halves),
// 256 threads = 32 cols x 8 og; thread: 2 oc-pairs x 2 rows.
// ---------------------------------------------------------------------------
template<int CINT, bool FROM_ATTN>
__global__ void __launch_bounds__(256) conv3x3_kernel(const float* __restrict__ xin,
                                                      const float* __restrict__ wt,
                                                      const float* __restrict__ bias,
                                                      float* __restrict__ out, int oc_off)
{
    constexpr int CCH = 16;
    __shared__ float ws[CCH * 9 * 32];   // [ci][k][oc_local]
    __shared__ float xs[CCH][4][36];

    const float* __restrict__ src = FROM_ATTN ? (const float*)g_attn : xin;

    const int b = blockIdx.y, y0 = blockIdx.x * 2;
    const int ocbase = blockIdx.z * 32;
    const int tid = threadIdx.x;
    const int x = tid & 31, og = tid >> 5;

    unsigned long long acc[2][2];
    acc[0][0] = acc[0][1] = acc[1][0] = acc[1][1] = 0ull;

    for (int c0 = 0; c0 < CINT; c0 += CCH) {
        __syncthreads();
        for (int i = tid; i < CCH * 9 * 32; i += 256) {
            int oc = i & 31;
            int r  = i >> 5;            // ci*9 + k
            int k  = r % 9, ci = r / 9;
            ws[i] = wt[((ocbase + oc) * CINT + c0 + ci) * 9 + k];
        }
        for (int i = tid; i < CCH * 4 * 34; i += 256) {
            int ci = i / 136;
            int r2 = i - ci * 136;
            int rr = r2 / 34, col = r2 - rr * 34;
            int yy = y0 - 1 + rr, xx = col - 1;
            float v = 0.f;
            if (yy >= 0 && yy < 32 && xx >= 0 && xx < 32)
                v = src[(b * CINT + c0 + ci) * LL + yy * 32 + xx];
            xs[ci][rr][col] = v;
        }
        __syncthreads();

        for (int ci = 0; ci < CCH; ci++) {
            unsigned long long x2[4][3];
#pragma unroll
            for (int rr = 0; rr < 4; rr++)
#pragma unroll
                for (int c = 0; c < 3; c++) {
                    float v = xs[ci][rr][x + c];
                    x2[rr][c] = pk2(v, v);
                }
            const float* wp = &ws[ci * 9 * 32 + og * 4];
#pragma unroll
            for (int k = 0; k < 9; k++) {
                const int ky = k / 3, c = k - ky * 3;
                ulonglong2 wA = *(const ulonglong2*)(wp + k * 32);
                acc[0][0] = fma2(wA.x, x2[ky][c],     acc[0][0]);
                acc[0][1] = fma2(wA.x, x2[ky + 1][c], acc[0][1]);
                acc[1][0] = fma2(wA.y, x2[ky][c],     acc[1][0]);
                acc[1][1] = fma2(wA.y, x2[ky + 1][c], acc[1][1]);
            }
        }
    }

#pragma unroll
    for (int p = 0; p < 2; p++) {
        const int oc0 = ocbase + og * 4 + 2 * p;
        float b0 = bias[oc0], b1 = bias[oc0 + 1];
#pragma unroll
        for (int r = 0; r < 2; r++) {
            float a, bb;
            upk2(acc[p][r], a, bb);
            out[(b * 128 + oc_off + oc0) * LL + (y0 + r) * 32 + x]     = a + b0;
            out[(b * 128 + oc_off + oc0 + 1) * LL + (y0 + r) * 32 + x] = bb + b1;
        }
    }
}

// ---------------------------------------------------------------------------
// Launch
// ---------------------------------------------------------------------------
extern "C" void kernel_launch(void* const* d_in, const int* in_sizes, int n_in,
                              void* d_out, int out_size)
{
    const float* x         = (const float*)d_in[0];
    const float* w_general = (const float*)d_in[1];
    const float* b_general = (const float*)d_in[2];
    const float* w_qkv     = (const float*)d_in[3];
    const float* b_qkv     = (const float*)d_in[4];
    const float* w_out     = (const float*)d_in[5];
    const float* b_out     = (const float*)d_in[6];
    const float* krh       = (const float*)d_in[7];
    const float* krw       = (const float*)d_in[8];
    float* out = (float*)d_out;

    cudaFuncSetAttribute(attn_kernel,
                         cudaFuncAttributeMaxDynamicSharedMemorySize, 51200);

    conv3x3_kernel<128, false><<<dim3(16, NB, 2), 256>>>(x, w_general, b_general, out, 0);

    qkv_kernel<<<dim3(32, NB), 192>>>(x, w_qkv, b_qkv);
    rel_kernel<<<dim3(32, NB * NHH), 1024>>>(krh, krw);
    attn_kernel<<<dim3(8, NB * NHH), 128, 51200>>>();
    combine_kernel<<<256, 256>>>();
    conv3x3_kernel<64, true><<<dim3(16, NB, 2), 256>>>(nullptr, w_out, b_out, out, 64);
}

// round 4
// speedup vs baseline: 1.5528x; 1.2480x over previous
#include <cuda_runtime.h>

#define NB   8
#define NHH  8
#define LL   1024
#define SQRT8 2.8284271247461903f

// ---------------------------------------------------------------------------
// f32x2 helpers
// ---------------------------------------------------------------------------
__device__ __forceinline__ unsigned long long pk2(float a, float b) {
    unsigned long long r;
    asm("mov.b64 %0, {%1,%2};" : "=l"(r) : "f"(a), "f"(b));
    return r;
}
__device__ __forceinline__ void upk2(unsigned long long v, float& a, float& b) {
    asm("mov.b64 {%0,%1}, %2;" : "=f"(a), "=f"(b) : "l"(v));
}
__device__ __forceinline__ unsigned long long fma2(unsigned long long a,
                                                   unsigned long long b,
                                                   unsigned long long c) {
    unsigned long long r;
    asm("fma.rn.f32x2 %0, %1, %2, %3;" : "=l"(r) : "l"(a), "l"(b), "l"(c));
    return r;
}

// ---------------------------------------------------------------------------
// Scratch
// ---------------------------------------------------------------------------
__device__ float g_Q[NB * NHH * 8192];
__device__ float g_K[NB * NHH * 8192];
__device__ float g_V[NB * NHH * 8192];
__device__ float g_RH[NB * NHH * 32768];   // [bh][m1][n1][n2]
__device__ float g_RW[NB * NHH * 32768];   // [bh][m1][n1][m2]
__device__ float g_attn[NB * 64 * LL];
__device__ float g_pacc[4 * 64 * 8 * LL];  // [split][bh][d][n]
__device__ float g_pS[4 * 64 * LL];        // [split][bh][n]

// ---------------------------------------------------------------------------
// Kernel 1: qkv 1x1 conv.  grid(32,8), 192 threads.
// ---------------------------------------------------------------------------
__global__ void __launch_bounds__(192) qkv_kernel(const float* __restrict__ x,
                                                  const float* __restrict__ w,
                                                  const float* __restrict__ bias)
{
    __shared__ float xs[128][36];
    const int b = blockIdx.y, chunk = blockIdx.x;
    const int tid = threadIdx.x;

    for (int i = tid; i < 128 * 32; i += 192) {
        int ci = i >> 5, p = i & 31;
        xs[ci][p] = x[(b * 128 + ci) * LL + chunk * 32 + p];
    }
    __syncthreads();

    const int oc = tid;
    unsigned long long acc[16];
#pragma unroll
    for (int j = 0; j < 16; j++) acc[j] = 0ull;

    const float4* wrow = (const float4*)(w + oc * 128);
#pragma unroll 8
    for (int c4 = 0; c4 < 32; c4++) {
        float4 w4 = __ldg(&wrow[c4]);
#pragma unroll
        for (int s = 0; s < 4; s++) {
            float wv = (s == 0) ? w4.x : (s == 1) ? w4.y : (s == 2) ? w4.z : w4.w;
            unsigned long long w2 = pk2(wv, wv);
            const ulonglong2* row = (const ulonglong2*)&xs[c4 * 4 + s][0];
#pragma unroll
            for (int j = 0; j < 8; j++) {
                ulonglong2 xv = row[j];
                acc[2 * j]     = fma2(w2, xv.x, acc[2 * j]);
                acc[2 * j + 1] = fma2(w2, xv.y, acc[2 * j + 1]);
            }
        }
    }

    float bv = bias[oc];
    float scale = 1.f;
    float* dst;
    int c;
    if (oc < 64)       { dst = g_Q; c = oc;       scale = SQRT8; }
    else if (oc < 128) { dst = g_K; c = oc - 64;  }
    else               { dst = g_V; c = oc - 128; }
    const int h = c >> 3, dk = c & 7;
    const int base = ((b * NHH + h) * 8 + dk) * LL + chunk * 32;
#pragma unroll
    for (int j = 0; j < 16; j++) {
        float a, bb;
        upk2(acc[j], a, bb);
        dst[base + 2 * j]     = (a  + bv) * scale;
        dst[base + 2 * j + 1] = (bb + bv) * scale;
    }
}

// ---------------------------------------------------------------------------
// Kernel 2: relative-logit precompute
// ---------------------------------------------------------------------------
__global__ void rel_kernel(const float* __restrict__ krh,
                           const float* __restrict__ krw)
{
    __shared__ float srh[63][9], srw[63][9];
    const int bh = blockIdx.y, m1 = blockIdx.x;
    const int tid = threadIdx.x;

    if (tid < 63 * 8) {
        int r = tid >> 3, d = tid & 7;
        srh[r][d] = krh[tid];
        srw[r][d] = krw[tid];
    }
    __syncthreads();

    const int n1 = tid >> 5, lane = tid & 31;
    const float* qp = g_Q + bh * 8192 + m1 * 32 + n1;
    float q[8];
#pragma unroll
    for (int d = 0; d < 8; d++) q[d] = qp[d * LL];

    const int ih = lane - n1 + 31;
    const int iw = lane - m1 + 31;
    float rh = 0.f, rw = 0.f;
#pragma unroll
    for (int d = 0; d < 8; d++) {
        rh += q[d] * srh[ih][d];
        rw += q[d] * srw[iw][d];
    }
    const int o = ((bh * 32 + m1) * 32 + n1) * 32 + lane;
    g_RH[o] = rh;
    g_RW[o] = rw;
}

// ---------------------------------------------------------------------------
// Kernel 3: attention, split-K=4.
// grid(8, 64): blockIdx.x = split*2 + chunk. 256 threads, 2 queries/thread.
// CTA: 512 queries x 256 keys. smem 34.8KB static. 8 warps/CTA.
// rh values preloaded to registers (8 per query).
// ---------------------------------------------------------------------------
__global__ void __launch_bounds__(256) attn_kernel()
{
    __shared__ float sK[2048];
    __shared__ float sV[2048];
    __shared__ float sRW[8 * 16 * 36];   // [m1l][n1l][m2], padded

    const int bh = blockIdx.y;
    const int chunk = blockIdx.x & 1;
    const int split = blockIdx.x >> 1;
    const int tid = threadIdx.x;

    const float4* Kg4 = (const float4*)(g_K + bh * 8192 + split * 2048);
    const float4* Vg4 = (const float4*)(g_V + bh * 8192 + split * 2048);
    float4* sK4 = (float4*)sK;
    float4* sV4 = (float4*)sV;
#pragma unroll
    for (int i = tid; i < 512; i += 256) {
        sK4[i] = Kg4[i];
        sV4[i] = Vg4[i];
    }
    const float* RWg = g_RW + bh * 32768 + split * 8192 + chunk * 512;
    for (int i = tid; i < 4096; i += 256) {
        int m1l = i >> 9, r = i & 511;
        int n1l = r >> 5, m2 = r & 31;
        sRW[(m1l * 16 + n1l) * 36 + m2] = RWg[m1l * 1024 + n1l * 32 + m2];
    }
    __syncthreads();

    const int n1t = tid >> 4, j = tid & 15;
    const int n0 = chunk * 512 + n1t * 32 + j;   // query 0; query 1 = n0+16

    // preload rh for all 8 local m1
    const float* RHg = g_RH + bh * 32768 + split * 8192;
    float rh0[8], rh1[8];
#pragma unroll
    for (int m1l = 0; m1l < 8; m1l++) {
        rh0[m1l] = RHg[m1l * 1024 + n0]      - 18.f;
        rh1[m1l] = RHg[m1l * 1024 + n0 + 16] - 18.f;
    }

    const ulonglong2* qg = (const ulonglong2*)(g_Q + bh * 8192 + n0 * 8);
    ulonglong2 qa = qg[0], qb = qg[1];
    const ulonglong2* qh = (const ulonglong2*)(g_Q + bh * 8192 + (n0 + 16) * 8);
    ulonglong2 qc = qh[0], qd = qh[1];
    unsigned long long q0[4] = { qa.x, qa.y, qb.x, qb.y };
    unsigned long long q1[4] = { qc.x, qc.y, qd.x, qd.y };

    unsigned long long acc0[4] = {0,0,0,0}, acc1[4] = {0,0,0,0};
    float S0 = 0.f, S1 = 0.f;

#pragma unroll
    for (int m1l = 0; m1l < 8; m1l++) {
        const float r0 = rh0[m1l], r1 = rh1[m1l];
        const float* rwp = sRW + (m1l * 16 + n1t) * 36;
        const float* kb = sK + m1l * 256;
        const float* vb = sV + m1l * 256;

#pragma unroll 8
        for (int m2 = 0; m2 < 32; m2++) {
            ulonglong2 ka = *(const ulonglong2*)(kb + m2 * 8);
            ulonglong2 kc = *(const ulonglong2*)(kb + m2 * 8 + 4);
            float rw = rwp[m2];

            unsigned long long d0 = pk2(r0, rw);
            d0 = fma2(q0[0], ka.x, d0);
            d0 = fma2(q0[1], ka.y, d0);
            d0 = fma2(q0[2], kc.x, d0);
            d0 = fma2(q0[3], kc.y, d0);
            unsigned long long d1 = pk2(r1, rw);
            d1 = fma2(q1[0], ka.x, d1);
            d1 = fma2(q1[1], ka.y, d1);
            d1 = fma2(q1[2], kc.x, d1);
            d1 = fma2(q1[3], kc.y, d1);

            float a, b;
            upk2(d0, a, b);
            float p0 = __expf(a + b);
            upk2(d1, a, b);
            float p1 = __expf(a + b);
            S0 += p0;
            S1 += p1;
            unsigned long long P0 = pk2(p0, p0);
            unsigned long long P1 = pk2(p1, p1);

            ulonglong2 va = *(const ulonglong2*)(vb + m2 * 8);
            ulonglong2 vc = *(const ulonglong2*)(vb + m2 * 8 + 4);
            acc0[0] = fma2(P0, va.x, acc0[0]);
            acc0[1] = fma2(P0, va.y, acc0[1]);
            acc0[2] = fma2(P0, vc.x, acc0[2]);
            acc0[3] = fma2(P0, vc.y, acc0[3]);
            acc1[0] = fma2(P1, va.x, acc1[0]);
            acc1[1] = fma2(P1, va.y, acc1[1]);
            acc1[2] = fma2(P1, vc.x, acc1[2]);
            acc1[3] = fma2(P1, vc.y, acc1[3]);
        }
    }

    const int pb = split * 64 + bh;
#pragma unroll
    for (int jj = 0; jj < 4; jj++) {
        float a, b;
        upk2(acc0[jj], a, b);
        g_pacc[(pb * 8 + 2 * jj) * LL + n0]     = a;
        g_pacc[(pb * 8 + 2 * jj + 1) * LL + n0] = b;
        upk2(acc1[jj], a, b);
        g_pacc[(pb * 8 + 2 * jj) * LL + n0 + 16]     = a;
        g_pacc[(pb * 8 + 2 * jj + 1) * LL + n0 + 16] = b;
    }
    g_pS[pb * LL + n0]      = S0;
    g_pS[pb * LL + n0 + 16] = S1;
}

// ---------------------------------------------------------------------------
// Kernel 3b: split-K combine (4 splits) -> g_attn
// ---------------------------------------------------------------------------
__global__ void __launch_bounds__(256) combine_kernel()
{
    const int idx = blockIdx.x * 256 + threadIdx.x;   // 65536 total
    const int bh = idx >> 10, n = idx & 1023;
    float S = 0.f;
#pragma unroll
    for (int s = 0; s < 4; s++) S += g_pS[(s * 64 + bh) * LL + n];
    const float inv = 1.f / S;
#pragma unroll
    for (int d = 0; d < 8; d++) {
        float a = 0.f;
#pragma unroll
        for (int s = 0; s < 4; s++)
            a += g_pacc[((s * 64 + bh) * 8 + d) * LL + n];
        g_attn[(bh * 8 + d) * LL + n] = a * inv;
    }
}

// ---------------------------------------------------------------------------
// Kernel 4/5: 3x3 conv. grid(16 rowpairs, 8 b, 4 oc-sixteenths), 128 threads.
// Thread: 32 cols x 4 og; 2 oc-pairs x 2 rows = 8 outputs.
// ---------------------------------------------------------------------------
template<int CINT, bool FROM_ATTN>
__global__ void __launch_bounds__(128) conv3x3_kernel(const float* __restrict__ xin,
                                                      const float* __restrict__ wt,
                                                      const float* __restrict__ bias,
                                                      float* __restrict__ out, int oc_off)
{
    constexpr int CCH = 16;
    __shared__ float ws[CCH * 9 * 16];   // [ci][k][oc_local(16)]
    __shared__ float xs[CCH][4][36];

    const float* __restrict__ src = FROM_ATTN ? (const float*)g_attn : xin;

    const int b = blockIdx.y, y0 = blockIdx.x * 2;
    const int ocbase = blockIdx.z * 16;
    const int tid = threadIdx.x;
    const int x = tid & 31, og = tid >> 5;   // og in [0,4)

    unsigned long long acc[2][2];
    acc[0][0] = acc[0][1] = acc[1][0] = acc[1][1] = 0ull;

    for (int c0 = 0; c0 < CINT; c0 += CCH) {
        __syncthreads();
        for (int i = tid; i < CCH * 9 * 16; i += 128) {
            int oc = i & 15;
            int r  = i >> 4;            // ci*9 + k
            int k  = r % 9, ci = r / 9;
            ws[i] = wt[((ocbase + oc) * CINT + c0 + ci) * 9 + k];
        }
        for (int i = tid; i < CCH * 4 * 34; i += 128) {
            int ci = i / 136;
            int r2 = i - ci * 136;
            int rr = r2 / 34, col = r2 - rr * 34;
            int yy = y0 - 1 + rr, xx = col - 1;
            float v = 0.f;
            if (yy >= 0 && yy < 32 && xx >= 0 && xx < 32)
                v = src[(b * CINT + c0 + ci) * LL + yy * 32 + xx];
            xs[ci][rr][col] = v;
        }
        __syncthreads();

        for (int ci = 0; ci < CCH; ci++) {
            unsigned long long x2[4][3];
#pragma unroll
            for (int rr = 0; rr < 4; rr++)
#pragma unroll
                for (int c = 0; c < 3; c++) {
                    float v = xs[ci][rr][x + c];
                    x2[rr][c] = pk2(v, v);
                }
            const float* wp = &ws[ci * 144 + og * 4];
#pragma unroll
            for (int k = 0; k < 9; k++) {
                const int ky = k / 3, c = k - ky * 3;
                ulonglong2 wA = *(const ulonglong2*)(wp + k * 16);
                acc[0][0] = fma2(wA.x, x2[ky][c],     acc[0][0]);
                acc[0][1] = fma2(wA.x, x2[ky + 1][c], acc[0][1]);
                acc[1][0] = fma2(wA.y, x2[ky][c],     acc[1][0]);
                acc[1][1] = fma2(wA.y, x2[ky + 1][c], acc[1][1]);
            }
        }
    }

#pragma unroll
    for (int p = 0; p < 2; p++) {
        const int oc0 = ocbase + og * 4 + 2 * p;
        float b0 = bias[oc0], b1 = bias[oc0 + 1];
#pragma unroll
        for (int r = 0; r < 2; r++) {
            float a, bb;
            upk2(acc[p][r], a, bb);
            out[(b * 128 + oc_off + oc0) * LL + (y0 + r) * 32 + x]     = a + b0;
            out[(b * 128 + oc_off + oc0 + 1) * LL + (y0 + r) * 32 + x] = bb + b1;
        }
    }
}

// ---------------------------------------------------------------------------
// Launch: fork conv_general onto a side stream (independent branch), join at end.
// Statics are created on the first (uncaptured) correctness call; the event
// fork/join pattern is graph-capture legal.
// ---------------------------------------------------------------------------
extern "C" void kernel_launch(void* const* d_in, const int* in_sizes, int n_in,
                              void* d_out, int out_size)
{
    const float* x         = (const float*)d_in[0];
    const float* w_general = (const float*)d_in[1];
    const float* b_general = (const float*)d_in[2];
    const float* w_qkv     = (const float*)d_in[3];
    const float* b_qkv     = (const float*)d_in[4];
    const float* w_out     = (const float*)d_in[5];
    const float* b_out     = (const float*)d_in[6];
    const float* krh       = (const float*)d_in[7];
    const float* krw       = (const float*)d_in[8];
    float* out = (float*)d_out;

    static cudaStream_t s2 = nullptr;
    static cudaEvent_t ev_fork = nullptr, ev_join = nullptr;
    if (s2 == nullptr) {
        cudaStreamCreateWithFlags(&s2, cudaStreamNonBlocking);
        cudaEventCreateWithFlags(&ev_fork, cudaEventDisableTiming);
        cudaEventCreateWithFlags(&ev_join, cudaEventDisableTiming);
    }

    // fork: independent conv_general branch
    cudaEventRecord(ev_fork, 0);
    cudaStreamWaitEvent(s2, ev_fork, 0);
    conv3x3_kernel<128, false><<<dim3(16, NB, 4), 128, 0, s2>>>(x, w_general, b_general, out, 0);
    cudaEventRecord(ev_join, s2);

    // attention branch on main stream
    qkv_kernel<<<dim3(32, NB), 192>>>(x, w_qkv, b_qkv);
    rel_kernel<<<dim3(32, NB * NHH), 1024>>>(krh, krw);
    attn_kernel<<<dim3(8, NB * NHH), 256>>>();
    combine_kernel<<<256, 256>>>();
    conv3x3_kernel<64, true><<<dim3(16, NB, 4), 128>>>(nullptr, w_out, b_out, out, 64);

    // join
    cudaStreamWaitEvent(0, ev_join, 0);
}